// round 13
// baseline (speedup 1.0000x reference)
#include <cuda_runtime.h>
#include <cuda_bf16.h>
#include <cuda_fp16.h>
#include <cstdint>

#define NROWS  131072
#define DDIM   64
#define KCODES 1024
#define BM2    256          // rows per block in k_main
#define MARGIN 0.05f
#define FB_ROWS 32
#define FB_BPITCH 132

// ---------------- device scratch ----------------
__device__ float g_cnorm[KCODES];
__device__ int   g_cnt[KCODES];
__device__ int   g_off[KCODES];
__device__ int   g_cur[KCODES];
__device__ int   g_sorted[NROWS];
__device__ float g_isum[DDIM * KCODES];    // [d][code], written atomically-free
__device__ int   g_idx[NROWS];
__device__ float g_cbT[KCODES * DDIM];
__device__ __align__(16) __half g_cbh[KCODES * DDIM];  // [code][dim] fp16 codebook
__device__ int   g_nflag;
__device__ int   g_flag[NROWS];
__device__ unsigned long long g_pack[NROWS];

__device__ __forceinline__ uint32_t smem_u32(const void* p) {
    uint32_t a;
    asm("{ .reg .u64 t; cvta.to.shared.u64 t, %1; cvt.u32.u64 %0, t; }" : "=r"(a) : "l"(p));
    return a;
}
__device__ __forceinline__ uint32_t f32_sortable(float f) {
    uint32_t u = __float_as_uint(f);
    return (u & 0x80000000u) ? ~u : (u | 0x80000000u);
}

// ---------------- kernel 0: init scratch + codebook fp16 + norms ----------
__global__ void k_init(const float* __restrict__ cb, float* __restrict__ loss_slot) {
    int t = blockIdx.x * blockDim.x + threadIdx.x;   // 128 x 1024 = 131072
    g_pack[t] = 0xFFFFFFFFFFFFFFFFull;
    if (t < KCODES) {
        g_cnt[t] = 0;
        float s = 0.0f;
#pragma unroll
        for (int d = 0; d < DDIM; d++) {
            float v = cb[d * KCODES + t];
            s = fmaf(v, v, s);
            g_cbh[t * DDIM + d] = __float2half_rn(v);
        }
        g_cnorm[t] = s;
    }
    if (t == 0) { *loss_slot = 0.0f; g_nflag = 0; }
}

// ---------------- kernel 1: fp16 mma.sync approx distances + argmin + flags ----------
#define SMA_BYTES 36864
#define SMB_BYTES 147456
#define SM_MAIN_TOT (SMA_BYTES + SMB_BYTES + 4096)

#define MERGE(b, s, i, m) do {                                     \
    float ob = __shfl_xor_sync(0xffffffffu, (b), (m));             \
    float os = __shfl_xor_sync(0xffffffffu, (s), (m));             \
    int   oi = __shfl_xor_sync(0xffffffffu, (i), (m));             \
    float ns = fminf(fminf((s), os), fmaxf((b), ob));              \
    if (ob < (b) || (ob == (b) && oi < (i))) { (b) = ob; (i) = oi; } \
    (s) = ns;                                                      \
} while (0)

extern __shared__ char smemc[];
__global__ void __launch_bounds__(512, 1)
k_main(const float* __restrict__ x) {
    char* Abf = smemc;                       // row stride 144 B (72 fp16)
    char* Bbf = smemc + SMA_BYTES;           // row stride 144 B
    float* s_cn = (float*)(smemc + SMA_BYTES + SMB_BYTES);

    const int tid  = threadIdx.x;
    const int lane = tid & 31;
    const int wid  = tid >> 5;
    const int rowbase = blockIdx.x * BM2;

    {
        const uint4* gB = (const uint4*)g_cbh;
#pragma unroll
        for (int i = 0; i < 16; i++) {
            int v = tid + i * 512;
            int rc = v >> 3, d8 = v & 7;
            *(uint4*)(Bbf + rc * 144 + d8 * 16) = gB[v];
        }
    }
#pragma unroll
    for (int i = 0; i < 2; i++) s_cn[tid + i * 512] = g_cnorm[tid + i * 512];

    {
        const float4* xg = (const float4*)(x + (size_t)rowbase * DDIM);
#pragma unroll
        for (int i = 0; i < 8; i++) {
            int v = tid + i * 512;
            int r = v >> 4, d4 = (v & 15) << 2;
            float4 f = xg[v];
            uint32_t lo = ((uint32_t)__half_as_ushort(__float2half_rn(f.y)) << 16)
                        |  (uint32_t)__half_as_ushort(__float2half_rn(f.x));
            uint32_t hi = ((uint32_t)__half_as_ushort(__float2half_rn(f.w)) << 16)
                        |  (uint32_t)__half_as_ushort(__float2half_rn(f.z));
            *(uint2*)(Abf + r * 144 + d4 * 2) = make_uint2(lo, hi);
        }
    }
    __syncthreads();

    const uint32_t Abase = smem_u32(Abf);
    const uint32_t Bbase = smem_u32(Bbf);
    const int m0 = wid * 16;

    uint32_t a[4][4];
    {
        uint32_t ar = Abase + (uint32_t)(m0 + (lane & 15)) * 144 + (uint32_t)(lane >> 4) * 16;
#pragma unroll
        for (int kt = 0; kt < 4; kt++) {
            asm volatile("ldmatrix.sync.aligned.m8n8.x4.shared.b16 {%0,%1,%2,%3}, [%4];"
                : "=r"(a[kt][0]), "=r"(a[kt][1]), "=r"(a[kt][2]), "=r"(a[kt][3])
                : "r"(ar + kt * 32));
        }
    }

    float bl = 3.4e38f, sl = 3.4e38f, bh = 3.4e38f, sh = 3.4e38f;
    int   il = 0, ih = 0;
    const uint32_t baddr0 = Bbase + (uint32_t)(lane & 7) * 144 + (uint32_t)(lane >> 3) * 16;

#pragma unroll 4
    for (int nt = 0; nt < 128; nt++) {
        uint32_t b0, b1, b2, b3, b4, b5, b6, b7;
        uint32_t ad = baddr0 + (uint32_t)nt * (8 * 144);
        asm volatile("ldmatrix.sync.aligned.m8n8.x4.shared.b16 {%0,%1,%2,%3}, [%4];"
            : "=r"(b0), "=r"(b1), "=r"(b2), "=r"(b3) : "r"(ad));
        asm volatile("ldmatrix.sync.aligned.m8n8.x4.shared.b16 {%0,%1,%2,%3}, [%4];"
            : "=r"(b4), "=r"(b5), "=r"(b6), "=r"(b7) : "r"(ad + 64));

        float c0 = 0.f, c1 = 0.f, c2 = 0.f, c3 = 0.f;
        asm volatile("mma.sync.aligned.m16n8k16.row.col.f32.f16.f16.f32 "
            "{%0,%1,%2,%3}, {%4,%5,%6,%7}, {%8,%9}, {%0,%1,%2,%3};"
            : "+f"(c0), "+f"(c1), "+f"(c2), "+f"(c3)
            : "r"(a[0][0]), "r"(a[0][1]), "r"(a[0][2]), "r"(a[0][3]), "r"(b0), "r"(b1));
        asm volatile("mma.sync.aligned.m16n8k16.row.col.f32.f16.f16.f32 "
            "{%0,%1,%2,%3}, {%4,%5,%6,%7}, {%8,%9}, {%0,%1,%2,%3};"
            : "+f"(c0), "+f"(c1), "+f"(c2), "+f"(c3)
            : "r"(a[1][0]), "r"(a[1][1]), "r"(a[1][2]), "r"(a[1][3]), "r"(b2), "r"(b3));
        asm volatile("mma.sync.aligned.m16n8k16.row.col.f32.f16.f16.f32 "
            "{%0,%1,%2,%3}, {%4,%5,%6,%7}, {%8,%9}, {%0,%1,%2,%3};"
            : "+f"(c0), "+f"(c1), "+f"(c2), "+f"(c3)
            : "r"(a[2][0]), "r"(a[2][1]), "r"(a[2][2]), "r"(a[2][3]), "r"(b4), "r"(b5));
        asm volatile("mma.sync.aligned.m16n8k16.row.col.f32.f16.f16.f32 "
            "{%0,%1,%2,%3}, {%4,%5,%6,%7}, {%8,%9}, {%0,%1,%2,%3};"
            : "+f"(c0), "+f"(c1), "+f"(c2), "+f"(c3)
            : "r"(a[3][0]), "r"(a[3][1]), "r"(a[3][2]), "r"(a[3][3]), "r"(b6), "r"(b7));

        int code0 = nt * 8 + ((lane & 3) << 1);
        float cn0 = s_cn[code0], cn1 = s_cn[code0 + 1];
        float d0 = fmaf(-2.0f, c0, cn0);
        float d1 = fmaf(-2.0f, c1, cn1);
        float d2 = fmaf(-2.0f, c2, cn0);
        float d3 = fmaf(-2.0f, c3, cn1);
        if (d0 < bl) { sl = bl; bl = d0; il = code0;     } else if (d0 < sl) sl = d0;
        if (d1 < bl) { sl = bl; bl = d1; il = code0 + 1; } else if (d1 < sl) sl = d1;
        if (d2 < bh) { sh = bh; bh = d2; ih = code0;     } else if (d2 < sh) sh = d2;
        if (d3 < bh) { sh = bh; bh = d3; ih = code0 + 1; } else if (d3 < sh) sh = d3;
    }

    MERGE(bl, sl, il, 1); MERGE(bl, sl, il, 2);
    MERGE(bh, sh, ih, 1); MERGE(bh, sh, ih, 2);

    if ((lane & 3) == 0) {
        int g = lane >> 2;
        int row_lo = rowbase + m0 + g;
        int row_hi = row_lo + 8;
        g_idx[row_lo] = il;
        g_idx[row_hi] = ih;
        if (sl - bl < MARGIN) { int p = atomicAdd(&g_nflag, 1); g_flag[p] = row_lo; }
        if (sh - bh < MARGIN) { int p = atomicAdd(&g_nflag, 1); g_flag[p] = row_hi; }
    }
}

// ---------------- kernel 1b: exact fp32 re-solve, 32 rows x 128-code eighth ----
__global__ void __launch_bounds__(256)
k_fallback(const float* __restrict__ x, const float* __restrict__ cb) {
    float* As = (float*)smemc;                 // [64][FB_ROWS]  (8 KB)
    float* Bs = As + DDIM * FB_ROWS;           // [64][FB_BPITCH] (33.8 KB)

    const int tid = threadIdx.x;
    const int tx = tid & 15;
    const int ty = tid >> 4;
    const int eighth = blockIdx.x & 7;
    const int tile0  = blockIdx.x >> 3;
    const int ntiles = gridDim.x >> 3;
    const int count = g_nflag;
    const int kc = eighth * 128;

    for (int base = tile0 * FB_ROWS; base < count; base += ntiles * FB_ROWS) {
        __syncthreads();
#pragma unroll
        for (int i = 0; i < 2; i++) {
            int v = tid + i * 256;
            int r = v >> 4, d4 = (v & 15) << 2;
            int fi = base + r; if (fi > count - 1) fi = count - 1;
            int fr = g_flag[fi];
            float4 t4 = *(const float4*)(x + (size_t)fr * DDIM + d4);
            As[(d4 + 0) * FB_ROWS + r] = t4.x;
            As[(d4 + 1) * FB_ROWS + r] = t4.y;
            As[(d4 + 2) * FB_ROWS + r] = t4.z;
            As[(d4 + 3) * FB_ROWS + r] = t4.w;
        }
#pragma unroll
        for (int i = 0; i < 8; i++) {
            int v = tid + i * 256;
            int d = v >> 5, c4 = (v & 31) << 2;
            *(float4*)(Bs + d * FB_BPITCH + c4) = *(const float4*)(cb + d * KCODES + kc + c4);
        }
        __syncthreads();

        float best0 = 3.4e38f, best1 = 3.4e38f;
        int   bidx0 = 0, bidx1 = 0;
        float acc0[8], acc1[8];
#pragma unroll
        for (int j = 0; j < 8; j++) { acc0[j] = 0.0f; acc1[j] = 0.0f; }

#pragma unroll 16
        for (int d = 0; d < DDIM; d++) {
            float a0 = As[d * FB_ROWS + ty];
            float a1 = As[d * FB_ROWS + ty + 16];
            float4 q0 = *(const float4*)(Bs + d * FB_BPITCH + tx * 8);
            float4 q1 = *(const float4*)(Bs + d * FB_BPITCH + tx * 8 + 4);
            acc0[0] = fmaf(a0, q0.x, acc0[0]);
            acc0[1] = fmaf(a0, q0.y, acc0[1]);
            acc0[2] = fmaf(a0, q0.z, acc0[2]);
            acc0[3] = fmaf(a0, q0.w, acc0[3]);
            acc0[4] = fmaf(a0, q1.x, acc0[4]);
            acc0[5] = fmaf(a0, q1.y, acc0[5]);
            acc0[6] = fmaf(a0, q1.z, acc0[6]);
            acc0[7] = fmaf(a0, q1.w, acc0[7]);
            acc1[0] = fmaf(a1, q0.x, acc1[0]);
            acc1[1] = fmaf(a1, q0.y, acc1[1]);
            acc1[2] = fmaf(a1, q0.z, acc1[2]);
            acc1[3] = fmaf(a1, q0.w, acc1[3]);
            acc1[4] = fmaf(a1, q1.x, acc1[4]);
            acc1[5] = fmaf(a1, q1.y, acc1[5]);
            acc1[6] = fmaf(a1, q1.z, acc1[6]);
            acc1[7] = fmaf(a1, q1.w, acc1[7]);
        }

#pragma unroll
        for (int j = 0; j < 8; j++) {
            int kidx = kc + tx * 8 + j;
            float cn = __ldg(&g_cnorm[kidx]);
            float dist0 = fmaf(-2.0f, acc0[j], cn);
            float dist1 = fmaf(-2.0f, acc1[j], cn);
            if (dist0 < best0) { best0 = dist0; bidx0 = kidx; }
            if (dist1 < best1) { best1 = dist1; bidx1 = kidx; }
        }

#pragma unroll
        for (int m = 1; m < 16; m <<= 1) {
            float ob = __shfl_xor_sync(0xffffffffu, best0, m);
            int   oi = __shfl_xor_sync(0xffffffffu, bidx0, m);
            if (ob < best0 || (ob == best0 && oi < bidx0)) { best0 = ob; bidx0 = oi; }
            float ob1 = __shfl_xor_sync(0xffffffffu, best1, m);
            int   oi1 = __shfl_xor_sync(0xffffffffu, bidx1, m);
            if (ob1 < best1 || (ob1 == best1 && oi1 < bidx1)) { best1 = ob1; bidx1 = oi1; }
        }
        if (tx == 0) {
            if (base + ty < count) {
                unsigned long long key =
                    ((unsigned long long)f32_sortable(best0) << 32) | (uint32_t)bidx0;
                atomicMin(&g_pack[g_flag[base + ty]], key);
            }
            if (base + ty + 16 < count) {
                unsigned long long key =
                    ((unsigned long long)f32_sortable(best1) << 32) | (uint32_t)bidx1;
                atomicMin(&g_pack[g_flag[base + ty + 16]], key);
            }
        }
        __syncthreads();
    }
}

// ---------------- kernel 1c: fold pack into g_idx + count histogram ----------------
__global__ void k_finalize() {
    int row = blockIdx.x * 1024 + threadIdx.x;   // 128 x 1024
    unsigned long long pk = g_pack[row];
    int code;
    if (pk != 0xFFFFFFFFFFFFFFFFull) {
        code = (int)(uint32_t)(pk & 0xFFFFFFFFull);
        g_idx[row] = code;
    } else {
        code = g_idx[row];
    }
    atomicAdd(&g_cnt[code], 1);
}

// ---------------- kernel 1d: exclusive prefix scan of counts (1 block) ----------
__global__ void k_scan() {
    int k = threadIdx.x;   // 1024
    int v = g_cnt[k];
    int lane = k & 31, warp = k >> 5;
    int s = v;
#pragma unroll
    for (int m = 1; m < 32; m <<= 1) {
        int o = __shfl_up_sync(0xffffffffu, s, m);
        if (lane >= m) s += o;
    }
    __shared__ int wsum[32];
    if (lane == 31) wsum[warp] = s;
    __syncthreads();
    if (warp == 0) {
        int w = wsum[lane];
#pragma unroll
        for (int m = 1; m < 32; m <<= 1) {
            int o = __shfl_up_sync(0xffffffffu, w, m);
            if (lane >= m) w += o;
        }
        wsum[lane] = w;
    }
    __syncthreads();
    int incl = s + (warp > 0 ? wsum[warp - 1] : 0);
    g_off[k] = incl - v;
    g_cur[k] = 0;
}

// ---------------- kernel 1e: place rows into code-sorted order ----------------
__global__ void k_place() {
    int row = blockIdx.x * 1024 + threadIdx.x;   // 128 x 1024
    int code = g_idx[row];
    int pos = atomicAdd(&g_cur[code], 1);
    g_sorted[g_off[code] + pos] = row;
}

// ---------------- kernel 1f: segment-sum per code (no atomics) ----------------
// one block per code, 64 threads (thread = dim). Coalesced row reads.
__global__ void __launch_bounds__(64)
k_isum(const float* __restrict__ x) {
    int code = blockIdx.x;
    int d = threadIdx.x;
    int off = g_off[code];
    int n = g_cnt[code];
    const int* sp = g_sorted + off;
    float a0 = 0.f, a1 = 0.f, a2 = 0.f, a3 = 0.f;
    int i = 0;
    for (; i + 4 <= n; i += 4) {
        int r0 = __ldg(sp + i + 0);
        int r1 = __ldg(sp + i + 1);
        int r2 = __ldg(sp + i + 2);
        int r3 = __ldg(sp + i + 3);
        a0 += x[(size_t)r0 * DDIM + d];
        a1 += x[(size_t)r1 * DDIM + d];
        a2 += x[(size_t)r2 * DDIM + d];
        a3 += x[(size_t)r3 * DDIM + d];
    }
    for (; i < n; i++) a0 += x[(size_t)__ldg(sp + i) * DDIM + d];
    g_isum[d * KCODES + code] = (a0 + a1) + (a2 + a3);
}

// ---------------- kernel 2: fused EMA stats + codebook update ----------------
__global__ void k_upd(const float* __restrict__ ema_cs,
                      const float* __restrict__ ema_sum,
                      float* __restrict__ out_cs,
                      float* __restrict__ out_sum,
                      float* __restrict__ out_cb) {
    int k = threadIdx.x;
    int d = blockIdx.x;
    float cs = fmaf(0.99f, ema_cs[k], 0.01f * (float)g_cnt[k]);

    __shared__ float red_[32];
    __shared__ float s_n;
    float s = cs;
#pragma unroll
    for (int m = 16; m >= 1; m >>= 1) s += __shfl_xor_sync(0xffffffffu, s, m);
    int lane = k & 31, warp = k >> 5;
    if (lane == 0) red_[warp] = s;
    __syncthreads();
    if (warp == 0) {
        float v = red_[lane];
#pragma unroll
        for (int m = 16; m >= 1; m >>= 1) v += __shfl_xor_sync(0xffffffffu, v, m);
        if (lane == 0) s_n = v;
    }
    __syncthreads();
    float n = s_n;
    float csize = ((cs + 1e-5f) / (n + KCODES * 1e-5f)) * n;
    if (d == 0) out_cs[k] = cs;

    int e = d * KCODES + k;
    float num = fmaf(0.99f, ema_sum[e], 0.01f * g_isum[e]);
    out_sum[e] = num;
    float ncb = num / csize;
    out_cb[e] = ncb;
    g_cbT[k * DDIM + d] = ncb;
}

// ---------------- kernel 3: quantize + loss ----------------
__global__ void k_quant(const float* __restrict__ x,
                        float* __restrict__ out_q, float* __restrict__ out_loss) {
    int t = blockIdx.x * 256 + threadIdx.x;
    float lsum = 0.0f;
#pragma unroll
    for (int it = 0; it < 2; it++) {
        int e4 = t + it * (4096 * 256);
        int r = e4 >> 4, d4 = (e4 & 15) << 2;
        int code = g_idx[r];
        float4 q4 = *(const float4*)(g_cbT + code * DDIM + d4);
        float4 x4 = *(const float4*)(x + ((size_t)e4 << 2));
        float dx0 = q4.x - x4.x, dx1 = q4.y - x4.y, dx2 = q4.z - x4.z, dx3 = q4.w - x4.w;
        float4 o;
        o.x = x4.x + dx0; o.y = x4.y + dx1; o.z = x4.z + dx2; o.w = x4.w + dx3;
        *(float4*)(out_q + ((size_t)e4 << 2)) = o;
        lsum = fmaf(dx0, dx0, lsum); lsum = fmaf(dx1, dx1, lsum);
        lsum = fmaf(dx2, dx2, lsum); lsum = fmaf(dx3, dx3, lsum);
    }
    __shared__ float red[8];
#pragma unroll
    for (int m = 16; m >= 1; m >>= 1) lsum += __shfl_xor_sync(0xffffffffu, lsum, m);
    int lane = threadIdx.x & 31, warp = threadIdx.x >> 5;
    if (lane == 0) red[warp] = lsum;
    __syncthreads();
    if (warp == 0) {
        float v = (lane < 8) ? red[lane] : 0.0f;
#pragma unroll
        for (int m = 4; m >= 1; m >>= 1) v += __shfl_xor_sync(0xffffffffu, v, m);
        if (lane == 0) atomicAdd(out_loss, v * (1.0f / 8388608.0f));
    }
}

// ---------------- launch ----------------
extern "C" void kernel_launch(void* const* d_in, const int* in_sizes, int n_in,
                              void* d_out, int out_size) {
    const float* x       = (const float*)d_in[0];
    const float* cb      = (const float*)d_in[1];
    const float* ema_cs  = (const float*)d_in[2];
    const float* ema_sum = (const float*)d_in[3];

    float* out      = (float*)d_out;
    float* out_q    = out;
    float* out_loss = out + 8388608;
    float* out_cb   = out_loss + 1;
    float* out_cs   = out_cb + 65536;
    float* out_sum  = out_cs + 1024;

    const int FB_SMEM = (DDIM * FB_ROWS + DDIM * FB_BPITCH) * 4;   // 41984 B
    static bool attr_set = false;
    if (!attr_set) {
        cudaFuncSetAttribute(k_main, cudaFuncAttributeMaxDynamicSharedMemorySize, SM_MAIN_TOT);
        cudaFuncSetAttribute(k_fallback, cudaFuncAttributeMaxDynamicSharedMemorySize, FB_SMEM);
        attr_set = true;
    }

    k_init<<<128, 1024>>>(cb, out_loss);
    k_main<<<NROWS / BM2, 512, SM_MAIN_TOT>>>(x);
    k_fallback<<<2048, 256, FB_SMEM>>>(x, cb);   // 256 tiles x 8 code-eighths
    k_finalize<<<128, 1024>>>();
    k_scan<<<1, 1024>>>();
    k_place<<<128, 1024>>>();
    k_isum<<<KCODES, 64>>>(x);
    k_upd<<<64, 1024>>>(ema_cs, ema_sum, out_cs, out_sum, out_cb);
    k_quant<<<4096, 256>>>(x, out_q, out_loss);
}

// round 14
// speedup vs baseline: 3.0890x; 3.0890x over previous
#include <cuda_runtime.h>
#include <cuda_bf16.h>
#include <cuda_fp16.h>
#include <cstdint>

#define NROWS  131072
#define DDIM   64
#define KCODES 1024
#define BM2    256          // rows per block in k_main
#define MARGIN 0.05f
#define FB_ROWS 32
#define FB_BPITCH 132
#define NREP   4            // g_isum replicas (contention reduction)

// ---------------- device scratch ----------------
__device__ float g_cnorm[KCODES];
__device__ float g_counts[KCODES];
__device__ float g_isum[NREP][DDIM * KCODES];   // D-MAJOR replicas: [rep][d][code]
__device__ int   g_idx[NROWS];
__device__ float g_cbT[KCODES * DDIM];
__device__ __align__(16) __half g_cbh[KCODES * DDIM];  // [code][dim] fp16 codebook
__device__ int   g_nflag;
__device__ int   g_flag[NROWS];
__device__ unsigned long long g_pack[NROWS];

__device__ __forceinline__ uint32_t smem_u32(const void* p) {
    uint32_t a;
    asm("{ .reg .u64 t; cvta.to.shared.u64 t, %1; cvt.u32.u64 %0, t; }" : "=r"(a) : "l"(p));
    return a;
}
__device__ __forceinline__ uint32_t f32_sortable(float f) {
    uint32_t u = __float_as_uint(f);
    return (u & 0x80000000u) ? ~u : (u | 0x80000000u);
}

// ---------------- kernel 0: init scratch + codebook fp16 + norms ----------
__global__ void k_init(const float* __restrict__ cb, float* __restrict__ loss_slot) {
    int t = blockIdx.x * blockDim.x + threadIdx.x;   // 128 x 1024 = 131072
    g_pack[t] = 0xFFFFFFFFFFFFFFFFull;
    if (t < DDIM * KCODES) {
#pragma unroll
        for (int r = 0; r < NREP; r++) g_isum[r][t] = 0.0f;
    }
    if (t < KCODES) {
        g_counts[t] = 0.0f;
        float s = 0.0f;
#pragma unroll
        for (int d = 0; d < DDIM; d++) {
            float v = cb[d * KCODES + t];
            s = fmaf(v, v, s);
            g_cbh[t * DDIM + d] = __float2half_rn(v);
        }
        g_cnorm[t] = s;
    }
    if (t == 0) { *loss_slot = 0.0f; g_nflag = 0; }
}

// ---------------- kernel 1: fp16 mma.sync approx distances + argmin + flags ----------
#define SMA_BYTES 36864
#define SMB_BYTES 147456
#define SM_MAIN_TOT (SMA_BYTES + SMB_BYTES + 4096)

#define MERGE(b, s, i, m) do {                                     \
    float ob = __shfl_xor_sync(0xffffffffu, (b), (m));             \
    float os = __shfl_xor_sync(0xffffffffu, (s), (m));             \
    int   oi = __shfl_xor_sync(0xffffffffu, (i), (m));             \
    float ns = fminf(fminf((s), os), fmaxf((b), ob));              \
    if (ob < (b) || (ob == (b) && oi < (i))) { (b) = ob; (i) = oi; } \
    (s) = ns;                                                      \
} while (0)

extern __shared__ char smemc[];
__global__ void __launch_bounds__(512, 1)
k_main(const float* __restrict__ x) {
    char* Abf = smemc;                       // row stride 144 B (72 fp16)
    char* Bbf = smemc + SMA_BYTES;           // row stride 144 B
    float* s_cn = (float*)(smemc + SMA_BYTES + SMB_BYTES);

    const int tid  = threadIdx.x;
    const int lane = tid & 31;
    const int wid  = tid >> 5;
    const int rowbase = blockIdx.x * BM2;

    {
        const uint4* gB = (const uint4*)g_cbh;
#pragma unroll
        for (int i = 0; i < 16; i++) {
            int v = tid + i * 512;
            int rc = v >> 3, d8 = v & 7;
            *(uint4*)(Bbf + rc * 144 + d8 * 16) = gB[v];
        }
    }
#pragma unroll
    for (int i = 0; i < 2; i++) s_cn[tid + i * 512] = g_cnorm[tid + i * 512];

    {
        const float4* xg = (const float4*)(x + (size_t)rowbase * DDIM);
#pragma unroll
        for (int i = 0; i < 8; i++) {
            int v = tid + i * 512;
            int r = v >> 4, d4 = (v & 15) << 2;
            float4 f = xg[v];
            uint32_t lo = ((uint32_t)__half_as_ushort(__float2half_rn(f.y)) << 16)
                        |  (uint32_t)__half_as_ushort(__float2half_rn(f.x));
            uint32_t hi = ((uint32_t)__half_as_ushort(__float2half_rn(f.w)) << 16)
                        |  (uint32_t)__half_as_ushort(__float2half_rn(f.z));
            *(uint2*)(Abf + r * 144 + d4 * 2) = make_uint2(lo, hi);
        }
    }
    __syncthreads();

    const uint32_t Abase = smem_u32(Abf);
    const uint32_t Bbase = smem_u32(Bbf);
    const int m0 = wid * 16;

    uint32_t a[4][4];
    {
        uint32_t ar = Abase + (uint32_t)(m0 + (lane & 15)) * 144 + (uint32_t)(lane >> 4) * 16;
#pragma unroll
        for (int kt = 0; kt < 4; kt++) {
            asm volatile("ldmatrix.sync.aligned.m8n8.x4.shared.b16 {%0,%1,%2,%3}, [%4];"
                : "=r"(a[kt][0]), "=r"(a[kt][1]), "=r"(a[kt][2]), "=r"(a[kt][3])
                : "r"(ar + kt * 32));
        }
    }

    float bl = 3.4e38f, sl = 3.4e38f, bh = 3.4e38f, sh = 3.4e38f;
    int   il = 0, ih = 0;
    const uint32_t baddr0 = Bbase + (uint32_t)(lane & 7) * 144 + (uint32_t)(lane >> 3) * 16;

#pragma unroll 4
    for (int nt = 0; nt < 128; nt++) {
        uint32_t b0, b1, b2, b3, b4, b5, b6, b7;
        uint32_t ad = baddr0 + (uint32_t)nt * (8 * 144);
        asm volatile("ldmatrix.sync.aligned.m8n8.x4.shared.b16 {%0,%1,%2,%3}, [%4];"
            : "=r"(b0), "=r"(b1), "=r"(b2), "=r"(b3) : "r"(ad));
        asm volatile("ldmatrix.sync.aligned.m8n8.x4.shared.b16 {%0,%1,%2,%3}, [%4];"
            : "=r"(b4), "=r"(b5), "=r"(b6), "=r"(b7) : "r"(ad + 64));

        float c0 = 0.f, c1 = 0.f, c2 = 0.f, c3 = 0.f;
        asm volatile("mma.sync.aligned.m16n8k16.row.col.f32.f16.f16.f32 "
            "{%0,%1,%2,%3}, {%4,%5,%6,%7}, {%8,%9}, {%0,%1,%2,%3};"
            : "+f"(c0), "+f"(c1), "+f"(c2), "+f"(c3)
            : "r"(a[0][0]), "r"(a[0][1]), "r"(a[0][2]), "r"(a[0][3]), "r"(b0), "r"(b1));
        asm volatile("mma.sync.aligned.m16n8k16.row.col.f32.f16.f16.f32 "
            "{%0,%1,%2,%3}, {%4,%5,%6,%7}, {%8,%9}, {%0,%1,%2,%3};"
            : "+f"(c0), "+f"(c1), "+f"(c2), "+f"(c3)
            : "r"(a[1][0]), "r"(a[1][1]), "r"(a[1][2]), "r"(a[1][3]), "r"(b2), "r"(b3));
        asm volatile("mma.sync.aligned.m16n8k16.row.col.f32.f16.f16.f32 "
            "{%0,%1,%2,%3}, {%4,%5,%6,%7}, {%8,%9}, {%0,%1,%2,%3};"
            : "+f"(c0), "+f"(c1), "+f"(c2), "+f"(c3)
            : "r"(a[2][0]), "r"(a[2][1]), "r"(a[2][2]), "r"(a[2][3]), "r"(b4), "r"(b5));
        asm volatile("mma.sync.aligned.m16n8k16.row.col.f32.f16.f16.f32 "
            "{%0,%1,%2,%3}, {%4,%5,%6,%7}, {%8,%9}, {%0,%1,%2,%3};"
            : "+f"(c0), "+f"(c1), "+f"(c2), "+f"(c3)
            : "r"(a[3][0]), "r"(a[3][1]), "r"(a[3][2]), "r"(a[3][3]), "r"(b6), "r"(b7));

        int code0 = nt * 8 + ((lane & 3) << 1);
        float cn0 = s_cn[code0], cn1 = s_cn[code0 + 1];
        float d0 = fmaf(-2.0f, c0, cn0);
        float d1 = fmaf(-2.0f, c1, cn1);
        float d2 = fmaf(-2.0f, c2, cn0);
        float d3 = fmaf(-2.0f, c3, cn1);
        if (d0 < bl) { sl = bl; bl = d0; il = code0;     } else if (d0 < sl) sl = d0;
        if (d1 < bl) { sl = bl; bl = d1; il = code0 + 1; } else if (d1 < sl) sl = d1;
        if (d2 < bh) { sh = bh; bh = d2; ih = code0;     } else if (d2 < sh) sh = d2;
        if (d3 < bh) { sh = bh; bh = d3; ih = code0 + 1; } else if (d3 < sh) sh = d3;
    }

    MERGE(bl, sl, il, 1); MERGE(bl, sl, il, 2);
    MERGE(bh, sh, ih, 1); MERGE(bh, sh, ih, 2);

    if ((lane & 3) == 0) {
        int g = lane >> 2;
        int row_lo = rowbase + m0 + g;
        int row_hi = row_lo + 8;
        g_idx[row_lo] = il;
        g_idx[row_hi] = ih;
        if (sl - bl < MARGIN) { int p = atomicAdd(&g_nflag, 1); g_flag[p] = row_lo; }
        if (sh - bh < MARGIN) { int p = atomicAdd(&g_nflag, 1); g_flag[p] = row_hi; }
    }
}

// ---------------- kernel 1b: exact fp32 re-solve, 32 rows x 128-code eighth ----
__global__ void __launch_bounds__(256)
k_fallback(const float* __restrict__ x, const float* __restrict__ cb) {
    float* As = (float*)smemc;                 // [64][FB_ROWS]  (8 KB)
    float* Bs = As + DDIM * FB_ROWS;           // [64][FB_BPITCH] (33.8 KB)

    const int tid = threadIdx.x;
    const int tx = tid & 15;
    const int ty = tid >> 4;
    const int eighth = blockIdx.x & 7;
    const int tile0  = blockIdx.x >> 3;
    const int ntiles = gridDim.x >> 3;
    const int count = g_nflag;
    const int kc = eighth * 128;

    for (int base = tile0 * FB_ROWS; base < count; base += ntiles * FB_ROWS) {
        __syncthreads();
#pragma unroll
        for (int i = 0; i < 2; i++) {
            int v = tid + i * 256;
            int r = v >> 4, d4 = (v & 15) << 2;
            int fi = base + r; if (fi > count - 1) fi = count - 1;
            int fr = g_flag[fi];
            float4 t4 = *(const float4*)(x + (size_t)fr * DDIM + d4);
            As[(d4 + 0) * FB_ROWS + r] = t4.x;
            As[(d4 + 1) * FB_ROWS + r] = t4.y;
            As[(d4 + 2) * FB_ROWS + r] = t4.z;
            As[(d4 + 3) * FB_ROWS + r] = t4.w;
        }
#pragma unroll
        for (int i = 0; i < 8; i++) {
            int v = tid + i * 256;
            int d = v >> 5, c4 = (v & 31) << 2;
            *(float4*)(Bs + d * FB_BPITCH + c4) = *(const float4*)(cb + d * KCODES + kc + c4);
        }
        __syncthreads();

        float best0 = 3.4e38f, best1 = 3.4e38f;
        int   bidx0 = 0, bidx1 = 0;
        float acc0[8], acc1[8];
#pragma unroll
        for (int j = 0; j < 8; j++) { acc0[j] = 0.0f; acc1[j] = 0.0f; }

#pragma unroll 16
        for (int d = 0; d < DDIM; d++) {
            float a0 = As[d * FB_ROWS + ty];
            float a1 = As[d * FB_ROWS + ty + 16];
            float4 q0 = *(const float4*)(Bs + d * FB_BPITCH + tx * 8);
            float4 q1 = *(const float4*)(Bs + d * FB_BPITCH + tx * 8 + 4);
            acc0[0] = fmaf(a0, q0.x, acc0[0]);
            acc0[1] = fmaf(a0, q0.y, acc0[1]);
            acc0[2] = fmaf(a0, q0.z, acc0[2]);
            acc0[3] = fmaf(a0, q0.w, acc0[3]);
            acc0[4] = fmaf(a0, q1.x, acc0[4]);
            acc0[5] = fmaf(a0, q1.y, acc0[5]);
            acc0[6] = fmaf(a0, q1.z, acc0[6]);
            acc0[7] = fmaf(a0, q1.w, acc0[7]);
            acc1[0] = fmaf(a1, q0.x, acc1[0]);
            acc1[1] = fmaf(a1, q0.y, acc1[1]);
            acc1[2] = fmaf(a1, q0.z, acc1[2]);
            acc1[3] = fmaf(a1, q0.w, acc1[3]);
            acc1[4] = fmaf(a1, q1.x, acc1[4]);
            acc1[5] = fmaf(a1, q1.y, acc1[5]);
            acc1[6] = fmaf(a1, q1.z, acc1[6]);
            acc1[7] = fmaf(a1, q1.w, acc1[7]);
        }

#pragma unroll
        for (int j = 0; j < 8; j++) {
            int kidx = kc + tx * 8 + j;
            float cn = __ldg(&g_cnorm[kidx]);
            float dist0 = fmaf(-2.0f, acc0[j], cn);
            float dist1 = fmaf(-2.0f, acc1[j], cn);
            if (dist0 < best0) { best0 = dist0; bidx0 = kidx; }
            if (dist1 < best1) { best1 = dist1; bidx1 = kidx; }
        }

#pragma unroll
        for (int m = 1; m < 16; m <<= 1) {
            float ob = __shfl_xor_sync(0xffffffffu, best0, m);
            int   oi = __shfl_xor_sync(0xffffffffu, bidx0, m);
            if (ob < best0 || (ob == best0 && oi < bidx0)) { best0 = ob; bidx0 = oi; }
            float ob1 = __shfl_xor_sync(0xffffffffu, best1, m);
            int   oi1 = __shfl_xor_sync(0xffffffffu, bidx1, m);
            if (ob1 < best1 || (ob1 == best1 && oi1 < bidx1)) { best1 = ob1; bidx1 = oi1; }
        }
        if (tx == 0) {
            if (base + ty < count) {
                unsigned long long key =
                    ((unsigned long long)f32_sortable(best0) << 32) | (uint32_t)bidx0;
                atomicMin(&g_pack[g_flag[base + ty]], key);
            }
            if (base + ty + 16 < count) {
                unsigned long long key =
                    ((unsigned long long)f32_sortable(best1) << 32) | (uint32_t)bidx1;
                atomicMin(&g_pack[g_flag[base + ty + 16]], key);
            }
        }
        __syncthreads();
    }
}

// ---------------- kernel 1c: scatter EMA stats (replicated isum) ----------------
__global__ void k_scatter(const float* __restrict__ x) {
    int t = blockIdx.x * 256 + threadIdx.x;   // 2048 blocks x 256 = 4*NROWS
    int row = t >> 2, q = t & 3;
    unsigned long long pk = g_pack[row];
    int code;
    if (pk != 0xFFFFFFFFFFFFFFFFull) {
        code = (int)(uint32_t)(pk & 0xFFFFFFFFull);
        if (q == 0) g_idx[row] = code;        // fix g_idx for k_quant
    } else {
        code = g_idx[row];
    }
    if (q == 0) atomicAdd(&g_counts[code], 1.0f);
    float* isum = g_isum[row & (NREP - 1)];
    const float4* xr = (const float4*)(x + (size_t)row * DDIM + q * 16);
#pragma unroll
    for (int j = 0; j < 4; j++) {
        float4 f = xr[j];
        int d = q * 16 + j * 4;
        atomicAdd(&isum[(d + 0) * KCODES + code], f.x);
        atomicAdd(&isum[(d + 1) * KCODES + code], f.y);
        atomicAdd(&isum[(d + 2) * KCODES + code], f.z);
        atomicAdd(&isum[(d + 3) * KCODES + code], f.w);
    }
}

// ---------------- kernel 2: fused EMA stats + codebook update ----------------
__global__ void k_upd(const float* __restrict__ ema_cs,
                      const float* __restrict__ ema_sum,
                      float* __restrict__ out_cs,
                      float* __restrict__ out_sum,
                      float* __restrict__ out_cb) {
    int k = threadIdx.x;
    int d = blockIdx.x;
    float cs = fmaf(0.99f, ema_cs[k], 0.01f * g_counts[k]);

    __shared__ float red_[32];
    __shared__ float s_n;
    float s = cs;
#pragma unroll
    for (int m = 16; m >= 1; m >>= 1) s += __shfl_xor_sync(0xffffffffu, s, m);
    int lane = k & 31, warp = k >> 5;
    if (lane == 0) red_[warp] = s;
    __syncthreads();
    if (warp == 0) {
        float v = red_[lane];
#pragma unroll
        for (int m = 16; m >= 1; m >>= 1) v += __shfl_xor_sync(0xffffffffu, v, m);
        if (lane == 0) s_n = v;
    }
    __syncthreads();
    float n = s_n;
    float csize = ((cs + 1e-5f) / (n + KCODES * 1e-5f)) * n;
    if (d == 0) out_cs[k] = cs;

    int e = d * KCODES + k;
    float isum = (g_isum[0][e] + g_isum[1][e]) + (g_isum[2][e] + g_isum[3][e]);
    float num = fmaf(0.99f, ema_sum[e], 0.01f * isum);
    out_sum[e] = num;
    float ncb = num / csize;
    out_cb[e] = ncb;
    g_cbT[k * DDIM + d] = ncb;
}

// ---------------- kernel 3: quantize + loss ----------------
__global__ void k_quant(const float* __restrict__ x,
                        float* __restrict__ out_q, float* __restrict__ out_loss) {
    int t = blockIdx.x * 256 + threadIdx.x;
    float lsum = 0.0f;
#pragma unroll
    for (int it = 0; it < 2; it++) {
        int e4 = t + it * (4096 * 256);
        int r = e4 >> 4, d4 = (e4 & 15) << 2;
        int code = g_idx[r];
        float4 q4 = *(const float4*)(g_cbT + code * DDIM + d4);
        float4 x4 = *(const float4*)(x + ((size_t)e4 << 2));
        float dx0 = q4.x - x4.x, dx1 = q4.y - x4.y, dx2 = q4.z - x4.z, dx3 = q4.w - x4.w;
        float4 o;
        o.x = x4.x + dx0; o.y = x4.y + dx1; o.z = x4.z + dx2; o.w = x4.w + dx3;
        *(float4*)(out_q + ((size_t)e4 << 2)) = o;
        lsum = fmaf(dx0, dx0, lsum); lsum = fmaf(dx1, dx1, lsum);
        lsum = fmaf(dx2, dx2, lsum); lsum = fmaf(dx3, dx3, lsum);
    }
    __shared__ float red[8];
#pragma unroll
    for (int m = 16; m >= 1; m >>= 1) lsum += __shfl_xor_sync(0xffffffffu, lsum, m);
    int lane = threadIdx.x & 31, warp = threadIdx.x >> 5;
    if (lane == 0) red[warp] = lsum;
    __syncthreads();
    if (warp == 0) {
        float v = (lane < 8) ? red[lane] : 0.0f;
#pragma unroll
        for (int m = 4; m >= 1; m >>= 1) v += __shfl_xor_sync(0xffffffffu, v, m);
        if (lane == 0) atomicAdd(out_loss, v * (1.0f / 8388608.0f));
    }
}

// ---------------- launch ----------------
extern "C" void kernel_launch(void* const* d_in, const int* in_sizes, int n_in,
                              void* d_out, int out_size) {
    const float* x       = (const float*)d_in[0];
    const float* cb      = (const float*)d_in[1];
    const float* ema_cs  = (const float*)d_in[2];
    const float* ema_sum = (const float*)d_in[3];

    float* out      = (float*)d_out;
    float* out_q    = out;
    float* out_loss = out + 8388608;
    float* out_cb   = out_loss + 1;
    float* out_cs   = out_cb + 65536;
    float* out_sum  = out_cs + 1024;

    const int FB_SMEM = (DDIM * FB_ROWS + DDIM * FB_BPITCH) * 4;   // 41984 B
    static bool attr_set = false;
    if (!attr_set) {
        cudaFuncSetAttribute(k_main, cudaFuncAttributeMaxDynamicSharedMemorySize, SM_MAIN_TOT);
        cudaFuncSetAttribute(k_fallback, cudaFuncAttributeMaxDynamicSharedMemorySize, FB_SMEM);
        attr_set = true;
    }

    k_init<<<128, 1024>>>(cb, out_loss);
    k_main<<<NROWS / BM2, 512, SM_MAIN_TOT>>>(x);
    k_fallback<<<2048, 256, FB_SMEM>>>(x, cb);   // 256 tiles x 8 code-eighths
    k_scatter<<<2048, 256>>>(x);
    k_upd<<<64, 1024>>>(ema_cs, ema_sum, out_cs, out_sum, out_cb);
    k_quant<<<4096, 256>>>(x, out_q, out_loss);
}

// round 15
// speedup vs baseline: 3.1181x; 1.0094x over previous
#include <cuda_runtime.h>
#include <cuda_bf16.h>
#include <cuda_fp16.h>
#include <cstdint>

#define NROWS  131072
#define DDIM   64
#define KCODES 1024
#define BM2    256          // rows per block in k_main
#define MARGIN 0.05f
#define FB_ROWS 32
#define FB_BPITCH 132
#define NREP   4            // g_isum replicas (contention reduction)

// ---------------- device scratch ----------------
__device__ float g_cnorm[KCODES];
__device__ float g_counts[KCODES];
__device__ float g_isum[NREP][DDIM * KCODES];   // D-MAJOR replicas: [rep][d][code]
__device__ int   g_idx[NROWS];
__device__ float g_cbT[KCODES * DDIM];
__device__ __align__(16) __half g_cbh[KCODES * DDIM];  // [code][dim] fp16 codebook
__device__ int   g_nflag;
__device__ int   g_flag[NROWS];
__device__ unsigned long long g_pack[NROWS];

__device__ __forceinline__ uint32_t smem_u32(const void* p) {
    uint32_t a;
    asm("{ .reg .u64 t; cvta.to.shared.u64 t, %1; cvt.u32.u64 %0, t; }" : "=r"(a) : "l"(p));
    return a;
}
__device__ __forceinline__ uint32_t f32_sortable(float f) {
    uint32_t u = __float_as_uint(f);
    return (u & 0x80000000u) ? ~u : (u | 0x80000000u);
}

// ---------------- kernel 0: init scratch + codebook fp16 + norms ----------
__global__ void k_init(const float* __restrict__ cb, float* __restrict__ loss_slot) {
    int t = blockIdx.x * blockDim.x + threadIdx.x;   // 128 x 1024 = 131072
    g_pack[t] = 0xFFFFFFFFFFFFFFFFull;
    if (t < DDIM * KCODES) {
#pragma unroll
        for (int r = 0; r < NREP; r++) g_isum[r][t] = 0.0f;
    }
    if (t < KCODES) {
        g_counts[t] = 0.0f;
        float s = 0.0f;
#pragma unroll
        for (int d = 0; d < DDIM; d++) {
            float v = cb[d * KCODES + t];
            s = fmaf(v, v, s);
            g_cbh[t * DDIM + d] = __float2half_rn(v);
        }
        g_cnorm[t] = s;
    }
    if (t == 0) { *loss_slot = 0.0f; g_nflag = 0; }
}

// ---------------- kernel 1: fp16 mma argmin + flags + FUSED scatter ----------
#define SMA_BYTES 36864
#define SMB_BYTES 147456
#define SMC_BYTES 4096
#define SMI_BYTES 1024
#define SM_MAIN_TOT (SMA_BYTES + SMB_BYTES + SMC_BYTES + SMI_BYTES)

#define MERGE(b, s, i, m) do {                                     \
    float ob = __shfl_xor_sync(0xffffffffu, (b), (m));             \
    float os = __shfl_xor_sync(0xffffffffu, (s), (m));             \
    int   oi = __shfl_xor_sync(0xffffffffu, (i), (m));             \
    float ns = fminf(fminf((s), os), fmaxf((b), ob));              \
    if (ob < (b) || (ob == (b) && oi < (i))) { (b) = ob; (i) = oi; } \
    (s) = ns;                                                      \
} while (0)

extern __shared__ char smemc[];
__global__ void __launch_bounds__(512, 1)
k_main(const float* __restrict__ x) {
    char* Abf = smemc;                       // row stride 144 B (72 fp16)
    char* Bbf = smemc + SMA_BYTES;           // row stride 144 B
    float* s_cn = (float*)(smemc + SMA_BYTES + SMB_BYTES);
    int* s_code = (int*)(smemc + SMA_BYTES + SMB_BYTES + SMC_BYTES);

    const int tid  = threadIdx.x;
    const int lane = tid & 31;
    const int wid  = tid >> 5;
    const int rowbase = blockIdx.x * BM2;

    {
        const uint4* gB = (const uint4*)g_cbh;
#pragma unroll
        for (int i = 0; i < 16; i++) {
            int v = tid + i * 512;
            int rc = v >> 3, d8 = v & 7;
            *(uint4*)(Bbf + rc * 144 + d8 * 16) = gB[v];
        }
    }
#pragma unroll
    for (int i = 0; i < 2; i++) s_cn[tid + i * 512] = g_cnorm[tid + i * 512];

    {
        const float4* xg = (const float4*)(x + (size_t)rowbase * DDIM);
#pragma unroll
        for (int i = 0; i < 8; i++) {
            int v = tid + i * 512;
            int r = v >> 4, d4 = (v & 15) << 2;
            float4 f = xg[v];
            uint32_t lo = ((uint32_t)__half_as_ushort(__float2half_rn(f.y)) << 16)
                        |  (uint32_t)__half_as_ushort(__float2half_rn(f.x));
            uint32_t hi = ((uint32_t)__half_as_ushort(__float2half_rn(f.w)) << 16)
                        |  (uint32_t)__half_as_ushort(__float2half_rn(f.z));
            *(uint2*)(Abf + r * 144 + d4 * 2) = make_uint2(lo, hi);
        }
    }
    __syncthreads();

    const uint32_t Abase = smem_u32(Abf);
    const uint32_t Bbase = smem_u32(Bbf);
    const int m0 = wid * 16;

    uint32_t a[4][4];
    {
        uint32_t ar = Abase + (uint32_t)(m0 + (lane & 15)) * 144 + (uint32_t)(lane >> 4) * 16;
#pragma unroll
        for (int kt = 0; kt < 4; kt++) {
            asm volatile("ldmatrix.sync.aligned.m8n8.x4.shared.b16 {%0,%1,%2,%3}, [%4];"
                : "=r"(a[kt][0]), "=r"(a[kt][1]), "=r"(a[kt][2]), "=r"(a[kt][3])
                : "r"(ar + kt * 32));
        }
    }

    float bl = 3.4e38f, sl = 3.4e38f, bh = 3.4e38f, sh = 3.4e38f;
    int   il = 0, ih = 0;
    const uint32_t baddr0 = Bbase + (uint32_t)(lane & 7) * 144 + (uint32_t)(lane >> 3) * 16;

#pragma unroll 4
    for (int nt = 0; nt < 128; nt++) {
        uint32_t b0, b1, b2, b3, b4, b5, b6, b7;
        uint32_t ad = baddr0 + (uint32_t)nt * (8 * 144);
        asm volatile("ldmatrix.sync.aligned.m8n8.x4.shared.b16 {%0,%1,%2,%3}, [%4];"
            : "=r"(b0), "=r"(b1), "=r"(b2), "=r"(b3) : "r"(ad));
        asm volatile("ldmatrix.sync.aligned.m8n8.x4.shared.b16 {%0,%1,%2,%3}, [%4];"
            : "=r"(b4), "=r"(b5), "=r"(b6), "=r"(b7) : "r"(ad + 64));

        float c0 = 0.f, c1 = 0.f, c2 = 0.f, c3 = 0.f;
        asm volatile("mma.sync.aligned.m16n8k16.row.col.f32.f16.f16.f32 "
            "{%0,%1,%2,%3}, {%4,%5,%6,%7}, {%8,%9}, {%0,%1,%2,%3};"
            : "+f"(c0), "+f"(c1), "+f"(c2), "+f"(c3)
            : "r"(a[0][0]), "r"(a[0][1]), "r"(a[0][2]), "r"(a[0][3]), "r"(b0), "r"(b1));
        asm volatile("mma.sync.aligned.m16n8k16.row.col.f32.f16.f16.f32 "
            "{%0,%1,%2,%3}, {%4,%5,%6,%7}, {%8,%9}, {%0,%1,%2,%3};"
            : "+f"(c0), "+f"(c1), "+f"(c2), "+f"(c3)
            : "r"(a[1][0]), "r"(a[1][1]), "r"(a[1][2]), "r"(a[1][3]), "r"(b2), "r"(b3));
        asm volatile("mma.sync.aligned.m16n8k16.row.col.f32.f16.f16.f32 "
            "{%0,%1,%2,%3}, {%4,%5,%6,%7}, {%8,%9}, {%0,%1,%2,%3};"
            : "+f"(c0), "+f"(c1), "+f"(c2), "+f"(c3)
            : "r"(a[2][0]), "r"(a[2][1]), "r"(a[2][2]), "r"(a[2][3]), "r"(b4), "r"(b5));
        asm volatile("mma.sync.aligned.m16n8k16.row.col.f32.f16.f16.f32 "
            "{%0,%1,%2,%3}, {%4,%5,%6,%7}, {%8,%9}, {%0,%1,%2,%3};"
            : "+f"(c0), "+f"(c1), "+f"(c2), "+f"(c3)
            : "r"(a[3][0]), "r"(a[3][1]), "r"(a[3][2]), "r"(a[3][3]), "r"(b6), "r"(b7));

        int code0 = nt * 8 + ((lane & 3) << 1);
        float cn0 = s_cn[code0], cn1 = s_cn[code0 + 1];
        float d0 = fmaf(-2.0f, c0, cn0);
        float d1 = fmaf(-2.0f, c1, cn1);
        float d2 = fmaf(-2.0f, c2, cn0);
        float d3 = fmaf(-2.0f, c3, cn1);
        if (d0 < bl) { sl = bl; bl = d0; il = code0;     } else if (d0 < sl) sl = d0;
        if (d1 < bl) { sl = bl; bl = d1; il = code0 + 1; } else if (d1 < sl) sl = d1;
        if (d2 < bh) { sh = bh; bh = d2; ih = code0;     } else if (d2 < sh) sh = d2;
        if (d3 < bh) { sh = bh; bh = d3; ih = code0 + 1; } else if (d3 < sh) sh = d3;
    }

    MERGE(bl, sl, il, 1); MERGE(bl, sl, il, 2);
    MERGE(bh, sh, ih, 1); MERGE(bh, sh, ih, 2);

    if ((lane & 3) == 0) {
        int g = lane >> 2;
        int row_lo = rowbase + m0 + g;
        int row_hi = row_lo + 8;
        g_idx[row_lo] = il;
        g_idx[row_hi] = ih;
        bool flag_lo = (sl - bl < MARGIN);
        bool flag_hi = (sh - bh < MARGIN);
        s_code[m0 + g]     = flag_lo ? -1 : il;
        s_code[m0 + g + 8] = flag_hi ? -1 : ih;
        if (flag_lo) { int p = atomicAdd(&g_nflag, 1); g_flag[p] = row_lo; }
        if (flag_hi) { int p = atomicAdd(&g_nflag, 1); g_flag[p] = row_hi; }
    }
    __syncthreads();

    // fused scatter for NON-flagged rows of this block (overlaps other blocks' MMA)
#pragma unroll
    for (int it = 0; it < 2; it++) {
        int task = tid + it * 512;          // 1024 tasks = 256 rows x 4 quarters
        int r = task >> 2, q = task & 3;
        int code = s_code[r];
        if (code >= 0) {
            int row = rowbase + r;
            if (q == 0) atomicAdd(&g_counts[code], 1.0f);
            float* isum = g_isum[row & (NREP - 1)];
            const float4* xr = (const float4*)(x + (size_t)row * DDIM + q * 16);
#pragma unroll
            for (int j = 0; j < 4; j++) {
                float4 f = xr[j];
                int d = q * 16 + j * 4;
                atomicAdd(&isum[(d + 0) * KCODES + code], f.x);
                atomicAdd(&isum[(d + 1) * KCODES + code], f.y);
                atomicAdd(&isum[(d + 2) * KCODES + code], f.z);
                atomicAdd(&isum[(d + 3) * KCODES + code], f.w);
            }
        }
    }
}

// ---------------- kernel 1b: exact fp32 re-solve, 32 rows x 128-code eighth ----
__global__ void __launch_bounds__(256)
k_fallback(const float* __restrict__ x, const float* __restrict__ cb) {
    float* As = (float*)smemc;                 // [64][FB_ROWS]  (8 KB)
    float* Bs = As + DDIM * FB_ROWS;           // [64][FB_BPITCH] (33.8 KB)

    const int tid = threadIdx.x;
    const int tx = tid & 15;
    const int ty = tid >> 4;
    const int eighth = blockIdx.x & 7;
    const int tile0  = blockIdx.x >> 3;
    const int ntiles = gridDim.x >> 3;
    const int count = g_nflag;
    const int kc = eighth * 128;

    for (int base = tile0 * FB_ROWS; base < count; base += ntiles * FB_ROWS) {
        __syncthreads();
#pragma unroll
        for (int i = 0; i < 2; i++) {
            int v = tid + i * 256;
            int r = v >> 4, d4 = (v & 15) << 2;
            int fi = base + r; if (fi > count - 1) fi = count - 1;
            int fr = g_flag[fi];
            float4 t4 = *(const float4*)(x + (size_t)fr * DDIM + d4);
            As[(d4 + 0) * FB_ROWS + r] = t4.x;
            As[(d4 + 1) * FB_ROWS + r] = t4.y;
            As[(d4 + 2) * FB_ROWS + r] = t4.z;
            As[(d4 + 3) * FB_ROWS + r] = t4.w;
        }
#pragma unroll
        for (int i = 0; i < 8; i++) {
            int v = tid + i * 256;
            int d = v >> 5, c4 = (v & 31) << 2;
            *(float4*)(Bs + d * FB_BPITCH + c4) = *(const float4*)(cb + d * KCODES + kc + c4);
        }
        __syncthreads();

        float best0 = 3.4e38f, best1 = 3.4e38f;
        int   bidx0 = 0, bidx1 = 0;
        float acc0[8], acc1[8];
#pragma unroll
        for (int j = 0; j < 8; j++) { acc0[j] = 0.0f; acc1[j] = 0.0f; }

#pragma unroll 16
        for (int d = 0; d < DDIM; d++) {
            float a0 = As[d * FB_ROWS + ty];
            float a1 = As[d * FB_ROWS + ty + 16];
            float4 q0 = *(const float4*)(Bs + d * FB_BPITCH + tx * 8);
            float4 q1 = *(const float4*)(Bs + d * FB_BPITCH + tx * 8 + 4);
            acc0[0] = fmaf(a0, q0.x, acc0[0]);
            acc0[1] = fmaf(a0, q0.y, acc0[1]);
            acc0[2] = fmaf(a0, q0.z, acc0[2]);
            acc0[3] = fmaf(a0, q0.w, acc0[3]);
            acc0[4] = fmaf(a0, q1.x, acc0[4]);
            acc0[5] = fmaf(a0, q1.y, acc0[5]);
            acc0[6] = fmaf(a0, q1.z, acc0[6]);
            acc0[7] = fmaf(a0, q1.w, acc0[7]);
            acc1[0] = fmaf(a1, q0.x, acc1[0]);
            acc1[1] = fmaf(a1, q0.y, acc1[1]);
            acc1[2] = fmaf(a1, q0.z, acc1[2]);
            acc1[3] = fmaf(a1, q0.w, acc1[3]);
            acc1[4] = fmaf(a1, q1.x, acc1[4]);
            acc1[5] = fmaf(a1, q1.y, acc1[5]);
            acc1[6] = fmaf(a1, q1.z, acc1[6]);
            acc1[7] = fmaf(a1, q1.w, acc1[7]);
        }

#pragma unroll
        for (int j = 0; j < 8; j++) {
            int kidx = kc + tx * 8 + j;
            float cn = __ldg(&g_cnorm[kidx]);
            float dist0 = fmaf(-2.0f, acc0[j], cn);
            float dist1 = fmaf(-2.0f, acc1[j], cn);
            if (dist0 < best0) { best0 = dist0; bidx0 = kidx; }
            if (dist1 < best1) { best1 = dist1; bidx1 = kidx; }
        }

#pragma unroll
        for (int m = 1; m < 16; m <<= 1) {
            float ob = __shfl_xor_sync(0xffffffffu, best0, m);
            int   oi = __shfl_xor_sync(0xffffffffu, bidx0, m);
            if (ob < best0 || (ob == best0 && oi < bidx0)) { best0 = ob; bidx0 = oi; }
            float ob1 = __shfl_xor_sync(0xffffffffu, best1, m);
            int   oi1 = __shfl_xor_sync(0xffffffffu, bidx1, m);
            if (ob1 < best1 || (ob1 == best1 && oi1 < bidx1)) { best1 = ob1; bidx1 = oi1; }
        }
        if (tx == 0) {
            if (base + ty < count) {
                unsigned long long key =
                    ((unsigned long long)f32_sortable(best0) << 32) | (uint32_t)bidx0;
                atomicMin(&g_pack[g_flag[base + ty]], key);
            }
            if (base + ty + 16 < count) {
                unsigned long long key =
                    ((unsigned long long)f32_sortable(best1) << 32) | (uint32_t)bidx1;
                atomicMin(&g_pack[g_flag[base + ty + 16]], key);
            }
        }
        __syncthreads();
    }
}

// ---------------- kernel 1c: scatter for FLAGGED rows only ----------------
__global__ void k_scatter_fl(const float* __restrict__ x) {
    int total = g_nflag * 4;
    for (int t = blockIdx.x * 256 + threadIdx.x; t < total; t += gridDim.x * 256) {
        int fi = t >> 2, q = t & 3;
        int row = g_flag[fi];
        int code = (int)(uint32_t)(g_pack[row] & 0xFFFFFFFFull);
        if (q == 0) {
            g_idx[row] = code;              // final index for k_quant
            atomicAdd(&g_counts[code], 1.0f);
        }
        float* isum = g_isum[row & (NREP - 1)];
        const float4* xr = (const float4*)(x + (size_t)row * DDIM + q * 16);
#pragma unroll
        for (int j = 0; j < 4; j++) {
            float4 f = xr[j];
            int d = q * 16 + j * 4;
            atomicAdd(&isum[(d + 0) * KCODES + code], f.x);
            atomicAdd(&isum[(d + 1) * KCODES + code], f.y);
            atomicAdd(&isum[(d + 2) * KCODES + code], f.z);
            atomicAdd(&isum[(d + 3) * KCODES + code], f.w);
        }
    }
}

// ---------------- kernel 2: fused EMA stats + codebook update ----------------
__global__ void k_upd(const float* __restrict__ ema_cs,
                      const float* __restrict__ ema_sum,
                      float* __restrict__ out_cs,
                      float* __restrict__ out_sum,
                      float* __restrict__ out_cb) {
    int k = threadIdx.x;
    int d = blockIdx.x;
    float cs = fmaf(0.99f, ema_cs[k], 0.01f * g_counts[k]);

    __shared__ float red_[32];
    __shared__ float s_n;
    float s = cs;
#pragma unroll
    for (int m = 16; m >= 1; m >>= 1) s += __shfl_xor_sync(0xffffffffu, s, m);
    int lane = k & 31, warp = k >> 5;
    if (lane == 0) red_[warp] = s;
    __syncthreads();
    if (warp == 0) {
        float v = red_[lane];
#pragma unroll
        for (int m = 16; m >= 1; m >>= 1) v += __shfl_xor_sync(0xffffffffu, v, m);
        if (lane == 0) s_n = v;
    }
    __syncthreads();
    float n = s_n;
    float csize = ((cs + 1e-5f) / (n + KCODES * 1e-5f)) * n;
    if (d == 0) out_cs[k] = cs;

    int e = d * KCODES + k;
    float isum = (g_isum[0][e] + g_isum[1][e]) + (g_isum[2][e] + g_isum[3][e]);
    float num = fmaf(0.99f, ema_sum[e], 0.01f * isum);
    out_sum[e] = num;
    float ncb = num / csize;
    out_cb[e] = ncb;
    g_cbT[k * DDIM + d] = ncb;
}

// ---------------- kernel 3: quantize + loss ----------------
__global__ void k_quant(const float* __restrict__ x,
                        float* __restrict__ out_q, float* __restrict__ out_loss) {
    int t = blockIdx.x * 256 + threadIdx.x;
    float lsum = 0.0f;
#pragma unroll
    for (int it = 0; it < 2; it++) {
        int e4 = t + it * (4096 * 256);
        int r = e4 >> 4, d4 = (e4 & 15) << 2;
        int code = g_idx[r];
        float4 q4 = *(const float4*)(g_cbT + code * DDIM + d4);
        float4 x4 = *(const float4*)(x + ((size_t)e4 << 2));
        float dx0 = q4.x - x4.x, dx1 = q4.y - x4.y, dx2 = q4.z - x4.z, dx3 = q4.w - x4.w;
        float4 o;
        o.x = x4.x + dx0; o.y = x4.y + dx1; o.z = x4.z + dx2; o.w = x4.w + dx3;
        *(float4*)(out_q + ((size_t)e4 << 2)) = o;
        lsum = fmaf(dx0, dx0, lsum); lsum = fmaf(dx1, dx1, lsum);
        lsum = fmaf(dx2, dx2, lsum); lsum = fmaf(dx3, dx3, lsum);
    }
    __shared__ float red[8];
#pragma unroll
    for (int m = 16; m >= 1; m >>= 1) lsum += __shfl_xor_sync(0xffffffffu, lsum, m);
    int lane = threadIdx.x & 31, warp = threadIdx.x >> 5;
    if (lane == 0) red[warp] = lsum;
    __syncthreads();
    if (warp == 0) {
        float v = (lane < 8) ? red[lane] : 0.0f;
#pragma unroll
        for (int m = 4; m >= 1; m >>= 1) v += __shfl_xor_sync(0xffffffffu, v, m);
        if (lane == 0) atomicAdd(out_loss, v * (1.0f / 8388608.0f));
    }
}

// ---------------- launch ----------------
extern "C" void kernel_launch(void* const* d_in, const int* in_sizes, int n_in,
                              void* d_out, int out_size) {
    const float* x       = (const float*)d_in[0];
    const float* cb      = (const float*)d_in[1];
    const float* ema_cs  = (const float*)d_in[2];
    const float* ema_sum = (const float*)d_in[3];

    float* out      = (float*)d_out;
    float* out_q    = out;
    float* out_loss = out + 8388608;
    float* out_cb   = out_loss + 1;
    float* out_cs   = out_cb + 65536;
    float* out_sum  = out_cs + 1024;

    const int FB_SMEM = (DDIM * FB_ROWS + DDIM * FB_BPITCH) * 4;   // 41984 B
    static bool attr_set = false;
    if (!attr_set) {
        cudaFuncSetAttribute(k_main, cudaFuncAttributeMaxDynamicSharedMemorySize, SM_MAIN_TOT);
        cudaFuncSetAttribute(k_fallback, cudaFuncAttributeMaxDynamicSharedMemorySize, FB_SMEM);
        attr_set = true;
    }

    k_init<<<128, 1024>>>(cb, out_loss);
    k_main<<<NROWS / BM2, 512, SM_MAIN_TOT>>>(x);
    k_fallback<<<2048, 256, FB_SMEM>>>(x, cb);   // 256 tiles x 8 code-eighths
    k_scatter_fl<<<64, 256>>>(x);
    k_upd<<<64, 1024>>>(ema_cs, ema_sum, out_cs, out_sum, out_cb);
    k_quant<<<4096, 256>>>(x, out_q, out_loss);
}